// round 16
// baseline (speedup 1.0000x reference)
#include <cuda_runtime.h>

#define BB 32
#define LL 64
#define NPAIRS 2016          // L*(L-1)/2
#define WPB 8                // warps (pair-units) per block
#define CHUNKS 252           // NPAIRS / WPB  -> blocks per batch

// pair p -> (l0<<6)|l1, constexpr-baked
struct T2Tab { int v[NPAIRS]; };
__host__ __device__ constexpr T2Tab make_t2() {
    T2Tab t{};
    int p = 0;
    for (int l1 = 1; l1 < 64; ++l1)
        for (int l0 = 0; l0 < l1; ++l0)
            t.v[p++] = (l0 << 6) | l1;
    return t;
}
__device__ constexpr T2Tab g_t2 = make_t2();

// cross-block scratch (zero at module load; kernel self-resets each call)
__device__ float    g_acc[BB];
__device__ unsigned g_cnt[BB];

__global__ void __launch_bounds__(256) gp_kernel(
        const float* __restrict__ x,
        const float* __restrict__ th0,
        const float* __restrict__ th1,
        const float* __restrict__ th2,
        const float* __restrict__ th3,
        float* __restrict__ out) {
    const int b     = blockIdx.x & 31;       // batch
    const int chunk = blockIdx.x >> 5;       // [0,252) pair-chunk
    const int tid   = threadIdx.x;
    const int warp  = tid >> 5;
    const int lane  = tid & 31;

    __shared__ int   so_s[LL];    // one-hot offsets o = l*4+c for batch b
    __shared__ float wsum[WPB];

    if (tid < LL) {
        float4 v = ((const float4*)x)[b * LL + tid];
        int c = v.y > 0.5f ? 1 : (v.z > 0.5f ? 2 : (v.w > 0.5f ? 3 : 0));
        so_s[tid] = tid * 4 + c;
    }
    __syncthreads();

    // ---- this warp: one pair, one batch; lanes = consecutive l2 ----
    const int pk = g_t2.v[warp * CHUNKS + chunk];   // strided for balance
    const int l0 = pk >> 6;
    const int l1 = pk & 63;

    const int base2 = so_s[l0] * 256 + so_s[l1];
    const float* __restrict__ row = th3 + (size_t)base2 * 256;

    float acc = (lane == 0) ? th2[base2] : 0.f;     // order-2 term
    const int l2 = l1 + 1 + lane;
    // strip covered in <=2 coalesced gathers (one theta3 row, nL<=4 each)
    if (l2 < LL)      acc += row[so_s[l2]];
    if (l2 + 32 < LL) acc += row[so_s[l2 + 32]];

    // order 0 + 1, folded into chunk-0 blocks (warp 0 lanes cover 2 pos each)
    if (chunk == 0 && warp == 0) {
        acc += th1[so_s[lane]] + th1[so_s[lane + 32]];
        if (lane == 0) acc += th0[0];
    }

    // warp butterfly + block merge
    #pragma unroll
    for (int off = 16; off > 0; off >>= 1)
        acc += __shfl_xor_sync(0xffffffffu, acc, off);
    if (lane == 0) wsum[warp] = acc;
    __syncthreads();

    if (tid == 0) {
        float t = 0.f;
        #pragma unroll
        for (int w = 0; w < WPB; w++) t += wsum[w];
        atomicAdd(&g_acc[b], t);
        __threadfence();
        unsigned done = atomicAdd(&g_cnt[b], 1u);
        if (done == CHUNKS - 1) {
            __threadfence();
            out[b] = g_acc[b];
            g_acc[b] = 0.f;      // reset for next replay
            g_cnt[b] = 0u;
        }
    }
}

extern "C" void kernel_launch(void* const* d_in, const int* in_sizes, int n_in,
                              void* d_out, int out_size) {
    const float* x   = (const float*)d_in[0];   // (B, L*C) one-hot
    const float* th0 = (const float*)d_in[1];   // (1,)
    const float* th1 = (const float*)d_in[2];   // (L, C)
    const float* th2 = (const float*)d_in[3];   // (L*C, L*C)
    const float* th3 = (const float*)d_in[4];   // (L*C, L*C, L*C)
    float* out = (float*)d_out;                 // (B, 1)

    gp_kernel<<<CHUNKS * BB, 256>>>(x, th0, th1, th2, th3, out);
}

// round 17
// speedup vs baseline: 1.7589x; 1.7589x over previous
#include <cuda_runtime.h>

#define BB 32
#define LL 64
#define NPAIRS 2016          // L*(L-1)/2
#define BPB 8                // blocks per batch
#define NT 1024              // threads per block

// Cross-block reduction scratch (zero at module load; kernel self-resets,
// so every call — correctness, capture, each graph replay — sees zeros).
__device__ float    g_acc[BB];
__device__ unsigned g_cnt[BB];

__global__ void __launch_bounds__(NT) gp_kernel(
        const float* __restrict__ x,
        const float* __restrict__ th0,
        const float* __restrict__ th1,
        const float* __restrict__ th2,
        const float* __restrict__ th3,
        float* __restrict__ out) {
    const int b     = blockIdx.x >> 3;       // batch
    const int blkid = blockIdx.x & 7;        // [0,8) within batch
    const int tid   = threadIdx.x;
    const int sub   = tid & 3;               // lane within 4-lane group
    const int grp   = tid >> 2;              // group in block [0,256)
    const int w     = grp >> 3;              // warp [0,32)
    const int gi    = grp & 7;               // group-slot in warp [0,8)
    // warp-consecutive pairs (uniform trip count), warps strided across the
    // full l1 range, blocks interleaved for balance
    const int p     = w * 64 + blkid * 8 + gi;    // [0,2048)

    __shared__ int   so_s[LL];    // flattened one-hot offsets o = l*4+c
    __shared__ float wsum[32];

    if (tid < LL) {
        float4 v = ((const float4*)x)[b * LL + tid];
        int c = v.y > 0.5f ? 1 : (v.z > 0.5f ? 2 : (v.w > 0.5f ? 3 : 0));
        so_s[tid] = tid * 4 + c;
    }
    __syncthreads();

    float acc = 0.f;

    if (p < NPAIRS) {
        // branchless decode: p = l1*(l1-1)/2 + l0, l0 < l1
        int l1 = (int)((1.0f + sqrtf(8.0f * (float)p + 1.0f)) * 0.5f);
        if ((l1 * (l1 - 1)) >> 1 > p) l1--;
        if (((l1 + 1) * l1) >> 1 <= p) l1++;
        const int l0 = p - ((l1 * (l1 - 1)) >> 1);

        const int base2 = so_s[l0] * 256 + so_s[l1];
        float t2 = (sub == 0) ? th2[base2] : 0.f;     // order-2 term

        const float* __restrict__ row = th3 + (size_t)base2 * 256;
        const int l2b = l1 + 1 + sub;

        // one-hot dot == scalar selection: row[so[l2]].
        // Fully unrolled + predicated; 4 independent accumulator chains.
        float a0 = 0.f, a1 = 0.f, a2 = 0.f, a3 = 0.f;
        #pragma unroll
        for (int t = 0; t < 4; t++) {
            int i = l2b + 4 * t;
            if (i < LL) a0 += row[so_s[i]];
        }
        #pragma unroll
        for (int t = 4; t < 8; t++) {
            int i = l2b + 4 * t;
            if (i < LL) a1 += row[so_s[i]];
        }
        #pragma unroll
        for (int t = 8; t < 12; t++) {
            int i = l2b + 4 * t;
            if (i < LL) a2 += row[so_s[i]];
        }
        #pragma unroll
        for (int t = 12; t < 16; t++) {
            int i = l2b + 4 * t;
            if (i < LL) a3 += row[so_s[i]];
        }
        acc = (a0 + a1) + (a2 + a3) + t2;
    }

    // order 0 + 1, folded into blkid-0 blocks (first 64 threads)
    if (blkid == 0 && tid < LL) {
        acc += th1[so_s[tid]];
        if (tid == 0) acc += th0[0];
    }

    // intra-block reduction (32 warps)
    #pragma unroll
    for (int off = 16; off > 0; off >>= 1)
        acc += __shfl_xor_sync(0xffffffffu, acc, off);
    const int warp = tid >> 5;
    if ((tid & 31) == 0) wsum[warp] = acc;
    __syncthreads();

    // cross-block: atomicAdd partial; last block for this batch finalizes
    if (tid == 0) {
        float t = 0.f;
        #pragma unroll
        for (int wi = 0; wi < 32; wi++) t += wsum[wi];
        atomicAdd(&g_acc[b], t);
        __threadfence();
        unsigned done = atomicAdd(&g_cnt[b], 1u);
        if (done == BPB - 1) {
            __threadfence();
            out[b] = g_acc[b];
            g_acc[b] = 0.f;      // reset for next replay
            g_cnt[b] = 0u;
        }
    }
}

extern "C" void kernel_launch(void* const* d_in, const int* in_sizes, int n_in,
                              void* d_out, int out_size) {
    const float* x   = (const float*)d_in[0];   // (B, L*C) one-hot
    const float* th0 = (const float*)d_in[1];   // (1,)
    const float* th1 = (const float*)d_in[2];   // (L, C)
    const float* th2 = (const float*)d_in[3];   // (L*C, L*C)
    const float* th3 = (const float*)d_in[4];   // (L*C, L*C, L*C)
    float* out = (float*)d_out;                 // (B, 1)

    gp_kernel<<<BB * BPB, NT>>>(x, th0, th1, th2, th3, out);
}